// round 1
// baseline (speedup 1.0000x reference)
#include <cuda_runtime.h>

#define BATCH   32
#define CIN     21
#define CH      128
#define LEN     4096
#define NTAP    2
#define NR      8
#define TL      64
#define THREADS 256

// scratch ping-pong buffers (device globals: allowed, no cudaMalloc)
__device__ float g_bufA[(size_t)BATCH * CH * LEN];
__device__ float g_bufB[(size_t)BATCH * CH * LEN];

__device__ __forceinline__ unsigned long long pack2(float a, float b) {
    unsigned long long r;
    asm("mov.b64 %0, {%1, %2};" : "=l"(r) : "f"(a), "f"(b));
    return r;
}
__device__ __forceinline__ void unpack2(unsigned long long v, float& a, float& b) {
    asm("mov.b64 {%0, %1}, %2;" : "=f"(a), "=f"(b) : "l"(v));
}
__device__ __forceinline__ unsigned long long ffma2(unsigned long long a,
                                                    unsigned long long b,
                                                    unsigned long long c) {
    unsigned long long d;
    asm("fma.rn.f32x2 %0, %1, %2, %3;" : "=l"(d) : "l"(a), "l"(b), "l"(c));
    return d;
}

// ---------------- initial projection: h0 = w0 @ x + b0 ----------------
__global__ void __launch_bounds__(THREADS) proj_kernel(
    const float* __restrict__ x, const float* __restrict__ w0,
    const float* __restrict__ b0, float* __restrict__ h)
{
    __shared__ float xs[CIN][128];
    __shared__ float ws[CH][CIN];
    __shared__ float bs[CH];

    const int b  = blockIdx.y;
    const int l0 = blockIdx.x * 128;
    const int t  = threadIdx.x;

    for (int e = t; e < CIN * 128; e += THREADS) {
        int i = e >> 7, l = e & 127;
        xs[i][l] = x[((size_t)b * CIN + i) * LEN + l0 + l];
    }
    for (int e = t; e < CH * CIN; e += THREADS)
        ws[e / CIN][e % CIN] = w0[e];
    if (t < CH) bs[t] = b0[t];
    __syncthreads();

    const int w = t >> 5, lane = t & 31;
    for (int oo = 0; oo < 16; oo++) {
        int o = w * 16 + oo;
        float a0 = bs[o], a1 = bs[o], a2 = bs[o], a3 = bs[o];
        #pragma unroll
        for (int i = 0; i < CIN; i++) {
            float wv = ws[o][i];
            a0 += wv * xs[i][lane];
            a1 += wv * xs[i][lane + 32];
            a2 += wv * xs[i][lane + 64];
            a3 += wv * xs[i][lane + 96];
        }
        float* dst = h + ((size_t)b * CH + o) * LEN + l0;
        dst[lane] = a0; dst[lane + 32] = a1; dst[lane + 64] = a2; dst[lane + 96] = a3;
    }
}

// ---------------- one WaveNet layer ----------------
// taps: k=0 at (l - off2), k=1 at (l - 1). off2 = pad (2 for layer 0, d+1 else)
__global__ void __launch_bounds__(THREADS, 1) layer_kernel(
    const float* __restrict__ hin, float* __restrict__ hout,
    float* __restrict__ skipout,
    const float* __restrict__ sw, const float* __restrict__ gw,
    const float* __restrict__ csw, const float* __restrict__ cgw,
    const float* __restrict__ rw, const float* __restrict__ kw,
    const float* __restrict__ z, int off2, int first)
{
    extern __shared__ float sm[];
    const int SPAN = TL + off2;
    float* hs  = sm;                      // [CH][SPAN]   input tile + left halo
    float* wA  = sm + CH * SPAN;          // [2][32][132] staged weights (reused)
    float* wB  = wA + 8448;               // [2][32][132]
    float* gsm = wB + 8448;               // [CH][68]     gated activations

    const int t     = threadIdx.x;
    const int jt    = t & 15;
    const int baseo = (t >> 4) * 8;
    const int b     = blockIdx.y;
    const int l0    = blockIdx.x * TL;

    // load h tile with left halo (zeros before sequence start)
    {
        const int warp = t >> 5, lane = t & 31;
        for (int c = warp; c < CH; c += 8) {
            const float* src = hin + ((size_t)b * CH + c) * LEN + (l0 - off2);
            float* dst = hs + c * SPAN;
            for (int p = lane; p < SPAN; p += 32)
                dst[p] = (l0 - off2 + p >= 0) ? src[p] : 0.f;
        }
    }

    unsigned long long accS[4][4], accG[4][4];
    #pragma unroll
    for (int a = 0; a < 4; a++)
        #pragma unroll
        for (int jj = 0; jj < 4; jj++) { accS[a][jj] = 0ULL; accG[a][jj] = 0ULL; }

    // ---- stage 1: signal/gate dilated convs (2 taps, K=128) ----
    for (int ci = 0; ci < 4; ci++) {
        __syncthreads();
        for (int e = t; e < 8192; e += THREADS) {
            int o = e >> 6, rem = e & 63, ic = rem >> 1, k = rem & 1;
            wA[(k * 32 + ic) * 132 + o] = sw[o * (CH * NTAP) + ci * 64 + rem];
            wB[(k * 32 + ic) * 132 + o] = gw[o * (CH * NTAP) + ci * 64 + rem];
        }
        __syncthreads();
        #pragma unroll 2
        for (int ic = 0; ic < 32; ic++) {
            const float* hrow = hs + (ci * 32 + ic) * SPAN;
            unsigned long long h0[4], h1[4];
            #pragma unroll
            for (int jj = 0; jj < 4; jj++) {
                float v0 = hrow[jt + 16 * jj];                 // tap k=0 (l - off2)
                float v1 = hrow[jt + 16 * jj + off2 - 1];      // tap k=1 (l - 1)
                h0[jj] = pack2(v0, v0);
                h1[jj] = pack2(v1, v1);
            }
            const float* wa0 = wA + ic * 132 + baseo;
            const float* wa1 = wA + (32 + ic) * 132 + baseo;
            const float* wb0 = wB + ic * 132 + baseo;
            const float* wb1 = wB + (32 + ic) * 132 + baseo;
            #pragma unroll
            for (int op = 0; op < 4; op++) {
                unsigned long long s0 = *(const unsigned long long*)(wa0 + 2 * op);
                unsigned long long s1 = *(const unsigned long long*)(wa1 + 2 * op);
                unsigned long long g0 = *(const unsigned long long*)(wb0 + 2 * op);
                unsigned long long g1 = *(const unsigned long long*)(wb1 + 2 * op);
                #pragma unroll
                for (int jj = 0; jj < 4; jj++) {
                    accS[op][jj] = ffma2(s0, h0[jj], accS[op][jj]);
                    accS[op][jj] = ffma2(s1, h1[jj], accS[op][jj]);
                    accG[op][jj] = ffma2(g0, h0[jj], accG[op][jj]);
                    accG[op][jj] = ffma2(g1, h1[jj], accG[op][jj]);
                }
            }
        }
    }

    // ---- conditioning + gating: g = signal * sigmoid(gate) -> gsm ----
    {
        float zv[4];
        #pragma unroll
        for (int jj = 0; jj < 4; jj++)
            zv[jj] = z[(size_t)b * LEN + l0 + jt + 16 * jj];
        #pragma unroll
        for (int op = 0; op < 4; op++) {
            int o = baseo + 2 * op;
            float cs0 = __ldg(csw + o), cs1 = __ldg(csw + o + 1);
            float cg0 = __ldg(cgw + o), cg1 = __ldg(cgw + o + 1);
            #pragma unroll
            for (int jj = 0; jj < 4; jj++) {
                float sa, sb, ga, gb;
                unpack2(accS[op][jj], sa, sb);
                unpack2(accG[op][jj], ga, gb);
                sa += cs0 * zv[jj];  sb += cs1 * zv[jj];
                ga += cg0 * zv[jj];  gb += cg1 * zv[jj];
                float va = sa * (1.f / (1.f + __expf(-ga)));
                float vb = sb * (1.f / (1.f + __expf(-gb)));
                gsm[o * 68 + jt + 16 * jj]       = va;
                gsm[(o + 1) * 68 + jt + 16 * jj] = vb;
            }
        }
    }

    // ---- stage 2: res/skip GEMMs over g (K=128) ----
    unsigned long long accR[4][4], accK[4][4];
    #pragma unroll
    for (int a = 0; a < 4; a++)
        #pragma unroll
        for (int jj = 0; jj < 4; jj++) { accR[a][jj] = 0ULL; accK[a][jj] = 0ULL; }

    for (int ci = 0; ci < 4; ci++) {
        __syncthreads();   // also orders gsm writes before gsm reads on ci==0
        for (int e = t; e < 4096; e += THREADS) {
            int o = e >> 5, ic = e & 31;
            wA[ic * 132 + o] = rw[o * CH + ci * 32 + ic];
            wB[ic * 132 + o] = kw[o * CH + ci * 32 + ic];
        }
        __syncthreads();
        #pragma unroll 2
        for (int ic = 0; ic < 32; ic++) {
            const float* grow = gsm + (ci * 32 + ic) * 68;
            unsigned long long gp[4];
            #pragma unroll
            for (int jj = 0; jj < 4; jj++) {
                float v = grow[jt + 16 * jj];
                gp[jj] = pack2(v, v);
            }
            const float* wra = wA + ic * 132 + baseo;
            const float* wka = wB + ic * 132 + baseo;
            #pragma unroll
            for (int op = 0; op < 4; op++) {
                unsigned long long wr = *(const unsigned long long*)(wra + 2 * op);
                unsigned long long wk = *(const unsigned long long*)(wka + 2 * op);
                #pragma unroll
                for (int jj = 0; jj < 4; jj++) {
                    accR[op][jj] = ffma2(wr, gp[jj], accR[op][jj]);
                    accK[op][jj] = ffma2(wk, gp[jj], accK[op][jj]);
                }
            }
        }
    }

    // ---- epilogue: h update + skip accumulation ----
    float* houtB = hout    + ((size_t)b * CH) * LEN + l0;
    float* skipB = skipout + ((size_t)b * CH) * LEN + l0;
    #pragma unroll
    for (int op = 0; op < 4; op++) {
        int o = baseo + 2 * op;
        #pragma unroll
        for (int jj = 0; jj < 4; jj++) {
            int j = jt + 16 * jj;
            float ra, rb, ka, kb;
            unpack2(accR[op][jj], ra, rb);
            unpack2(accK[op][jj], ka, kb);
            float ha, hb;
            if (first) {          // h = orig + res  (orig = this layer's input)
                ha = hs[o * SPAN + j + off2] + ra;
                hb = hs[(o + 1) * SPAN + j + off2] + rb;
            } else {              // h = res + g
                ha = gsm[o * 68 + j] + ra;
                hb = gsm[(o + 1) * 68 + j] + rb;
            }
            houtB[(size_t)o * LEN + j]       = ha;
            houtB[(size_t)(o + 1) * LEN + j] = hb;
            if (first) {
                skipB[(size_t)o * LEN + j]       = ka;
                skipB[(size_t)(o + 1) * LEN + j] = kb;
            } else {
                skipB[(size_t)o * LEN + j]       += ka;
                skipB[(size_t)(o + 1) * LEN + j] += kb;
            }
        }
    }
}

extern "C" void kernel_launch(void* const* d_in, const int* in_sizes, int n_in,
                              void* d_out, int out_size) {
    (void)in_sizes; (void)n_in; (void)out_size;
    const float* x   = (const float*)d_in[0];
    const float* z   = (const float*)d_in[1];
    const float* w0  = (const float*)d_in[2];
    const float* b0  = (const float*)d_in[3];
    const float* sw  = (const float*)d_in[4];
    const float* gw  = (const float*)d_in[5];
    const float* csw = (const float*)d_in[6];
    const float* cgw = (const float*)d_in[7];
    const float* rw  = (const float*)d_in[8];
    const float* kw  = (const float*)d_in[9];

    float* outH = (float*)d_out;                          // h        (B,C,L)
    float* outS = outH + (size_t)BATCH * CH * LEN;        // cum_skip (B,C,L)

    float *bufA, *bufB;
    cudaGetSymbolAddress((void**)&bufA, g_bufA);
    cudaGetSymbolAddress((void**)&bufB, g_bufB);

    int maxSmem = (CH * (TL + 129) + 25600) * 4;          // layer 7 worst case
    cudaFuncSetAttribute(layer_kernel,
                         cudaFuncAttributeMaxDynamicSharedMemorySize, maxSmem);

    proj_kernel<<<dim3(LEN / 128, BATCH), THREADS>>>(x, w0, b0, bufA);

    const float* cur = bufA;
    for (int ii = 0; ii < NR; ii++) {
        int d    = 1 << ii;
        int off2 = (ii == 0) ? 2 : d + 1;
        size_t smem = (size_t)(CH * (TL + off2) + 25600) * 4;
        float* nxt = (ii == NR - 1) ? outH : ((cur == bufA) ? bufB : bufA);
        layer_kernel<<<dim3(LEN / TL, BATCH), THREADS, smem>>>(
            cur, nxt, outS,
            sw + (size_t)ii * CH * CH * NTAP,
            gw + (size_t)ii * CH * CH * NTAP,
            csw + ii * CH, cgw + ii * CH,
            rw + (size_t)ii * CH * CH,
            kw + (size_t)ii * CH * CH,
            z, off2, ii == 0 ? 1 : 0);
        cur = nxt;
    }
}

// round 2
// speedup vs baseline: 1.4039x; 1.4039x over previous
#include <cuda_runtime.h>
#include <cuda_bf16.h>
#include <cstdint>

#define BATCH   32
#define CIN     21
#define CH      128
#define LEN     4096
#define NR      8
#define TL      64
#define THREADS 256
#define BPITCH  136   // bf16 elems per B-tile row ([n][k] layout)
#define WPITCH  40    // bf16 elems per A row ([m][k] chunk, 32 k + pad)
#define CHUNK   5120  // 128*WPITCH elems per (mat,half,kc) chunk

// ---------------- device scratch (no cudaMalloc allowed) ----------------
__device__ float g_bufA[(size_t)BATCH * CH * LEN];
__device__ float g_bufB[(size_t)BATCH * CH * LEN];
// stage1 weights: [layer][tap][mat(s,g)][half(hi,lo)][kc4][m128][WPITCH]
__device__ __nv_bfloat16 g_w1[(size_t)NR * 2 * 2 * 2 * 4 * CHUNK];
// stage2 weights: [layer][mat(res,skip)][half][kc4][m128][WPITCH]
__device__ __nv_bfloat16 g_w2[(size_t)NR * 2 * 2 * 4 * CHUNK];

// ---------------- helpers ----------------
__device__ __forceinline__ uint32_t sm_u32(const void* p) {
    return (uint32_t)__cvta_generic_to_shared(p);
}
__device__ __forceinline__ void ldm_x4(uint32_t* r, uint32_t addr) {
    asm volatile("ldmatrix.sync.aligned.m8n8.x4.shared.b16 {%0,%1,%2,%3}, [%4];"
                 : "=r"(r[0]), "=r"(r[1]), "=r"(r[2]), "=r"(r[3]) : "r"(addr));
}
__device__ __forceinline__ void ldm_x2(uint32_t* r, uint32_t addr) {
    asm volatile("ldmatrix.sync.aligned.m8n8.x2.shared.b16 {%0,%1}, [%2];"
                 : "=r"(r[0]), "=r"(r[1]) : "r"(addr));
}
__device__ __forceinline__ void mma16816(float* c, const uint32_t* a, const uint32_t* b) {
    asm volatile("mma.sync.aligned.m16n8k16.row.col.f32.bf16.bf16.f32 "
                 "{%0,%1,%2,%3}, {%4,%5,%6,%7}, {%8,%9}, {%0,%1,%2,%3};"
                 : "+f"(c[0]), "+f"(c[1]), "+f"(c[2]), "+f"(c[3])
                 : "r"(a[0]), "r"(a[1]), "r"(a[2]), "r"(a[3]),
                   "r"(b[0]), "r"(b[1]));
}

// ---------------- weight prep: split fp32 -> bf16 hi/lo, ldmatrix layout ----------------
__global__ void prep_w1(const float* __restrict__ sw, const float* __restrict__ gw) {
    int idx = blockIdx.x * blockDim.x + threadIdx.x;   // [layer][tap][mat][kc][m][kk]
    if (idx >= NR * 2 * 2 * 4 * 128 * 32) return;
    int kk = idx & 31; int r = idx >> 5;
    int m  = r & 127;  r >>= 7;
    int kc = r & 3;    r >>= 2;
    int mat = r & 1;   r >>= 1;
    int tap = r & 1;   r >>= 1;
    int layer = r;
    int i = kc * 32 + kk;
    const float* src = mat ? gw : sw;
    float v = src[(((size_t)layer * CH + m) * CH + i) * 2 + tap];
    __nv_bfloat16 hi = __float2bfloat16(v);
    __nv_bfloat16 lo = __float2bfloat16(v - __bfloat162float(hi));
    size_t base = ((size_t)((((layer * 2 + tap) * 2 + mat) * 2 + 0) * 4 + kc)) * CHUNK
                + (size_t)m * WPITCH + kk;
    g_w1[base] = hi;
    g_w1[base + (size_t)4 * CHUNK] = lo;   // half stride
}

__global__ void prep_w2(const float* __restrict__ rw, const float* __restrict__ kw) {
    int idx = blockIdx.x * blockDim.x + threadIdx.x;   // [layer][mat][kc][m][kk]
    if (idx >= NR * 2 * 4 * 128 * 32) return;
    int kk = idx & 31; int r = idx >> 5;
    int m  = r & 127;  r >>= 7;
    int kc = r & 3;    r >>= 2;
    int mat = r & 1;   r >>= 1;
    int layer = r;
    int i = kc * 32 + kk;
    const float* src = mat ? kw : rw;
    float v = src[((size_t)layer * CH + m) * CH + i];
    __nv_bfloat16 hi = __float2bfloat16(v);
    __nv_bfloat16 lo = __float2bfloat16(v - __bfloat162float(hi));
    size_t base = ((size_t)(((layer * 2 + mat) * 2 + 0) * 4 + kc)) * CHUNK
                + (size_t)m * WPITCH + kk;
    g_w2[base] = hi;
    g_w2[base + (size_t)4 * CHUNK] = lo;
}

// ---------------- initial projection: h0 = w0 @ x + b0 ----------------
__global__ void __launch_bounds__(THREADS) proj_kernel(
    const float* __restrict__ x, const float* __restrict__ w0,
    const float* __restrict__ b0, float* __restrict__ h)
{
    __shared__ float xs[CIN][128];
    __shared__ float ws[CH][CIN];
    __shared__ float bs[CH];

    const int b  = blockIdx.y;
    const int l0 = blockIdx.x * 128;
    const int t  = threadIdx.x;

    for (int e = t; e < CIN * 128; e += THREADS) {
        int i = e >> 7, l = e & 127;
        xs[i][l] = x[((size_t)b * CIN + i) * LEN + l0 + l];
    }
    for (int e = t; e < CH * CIN; e += THREADS)
        ws[e / CIN][e % CIN] = w0[e];
    if (t < CH) bs[t] = b0[t];
    __syncthreads();

    const int w = t >> 5, lane = t & 31;
    for (int oo = 0; oo < 16; oo++) {
        int o = w * 16 + oo;
        float a0 = bs[o], a1 = bs[o], a2 = bs[o], a3 = bs[o];
        #pragma unroll
        for (int i = 0; i < CIN; i++) {
            float wv = ws[o][i];
            a0 += wv * xs[i][lane];
            a1 += wv * xs[i][lane + 32];
            a2 += wv * xs[i][lane + 64];
            a3 += wv * xs[i][lane + 96];
        }
        float* dst = h + ((size_t)b * CH + o) * LEN + l0;
        dst[lane] = a0; dst[lane + 32] = a1; dst[lane + 64] = a2; dst[lane + 96] = a3;
    }
}

// ---------------- one WaveNet layer via mma.sync bf16x2 ----------------
// taps: tap0 at (l - off2), tap1 at (l - 1)
__global__ void __launch_bounds__(THREADS) layer_mma(
    const float* __restrict__ hin, float* __restrict__ hout,
    float* __restrict__ skipout,
    const __nv_bfloat16* __restrict__ w1, const __nv_bfloat16* __restrict__ w2,
    const float* __restrict__ csw, const float* __restrict__ cgw,
    const float* __restrict__ z, int off2, int first)
{
    extern __shared__ __align__(16) unsigned char smraw[];
    __nv_bfloat16* b0h = (__nv_bfloat16*)smraw;          // [64][BPITCH]
    __nv_bfloat16* b0l = b0h + 64 * BPITCH;
    __nv_bfloat16* b1h = b0l + 64 * BPITCH;
    __nv_bfloat16* b1l = b1h + 64 * BPITCH;
    __nv_bfloat16* wsm = b1l + 64 * BPITCH;              // [4][128][WPITCH]

    const int t = threadIdx.x, wid = t >> 5, lane = t & 31;
    const int gid = lane >> 2, tig = lane & 3;
    const int b = blockIdx.y, l0 = blockIdx.x * TL;

    // ---- load both shifted B windows, convert to bf16 hi/lo, [n][k] layout ----
    {
        const int s0 = l0 - off2, s1 = l0 - 1;
        for (int e = t; e < CH * TL; e += THREADS) {
            int ch = e >> 6, p = e & 63;
            const float* row = hin + (size_t)(b * CH + ch) * LEN;
            int q0 = s0 + p, q1 = s1 + p;
            float v0 = (q0 >= 0) ? row[q0] : 0.f;
            float v1 = (q1 >= 0) ? row[q1] : 0.f;
            __nv_bfloat16 h0 = __float2bfloat16(v0);
            b0h[p * BPITCH + ch] = h0;
            b0l[p * BPITCH + ch] = __float2bfloat16(v0 - __bfloat162float(h0));
            __nv_bfloat16 h1 = __float2bfloat16(v1);
            b1h[p * BPITCH + ch] = h1;
            b1l[p * BPITCH + ch] = __float2bfloat16(v1 - __bfloat162float(h1));
        }
    }

    float accS[8][4], accG[8][4];
    #pragma unroll
    for (int i = 0; i < 8; i++)
        #pragma unroll
        for (int j = 0; j < 4; j++) { accS[i][j] = 0.f; accG[i][j] = 0.f; }

    const uint32_t wbase = sm_u32(wsm);
    const int sel   = lane >> 3;
    const int arow0 = wid * 16 + ((sel & 1) << 3) + (lane & 7);
    const uint32_t acolB = (uint32_t)((sel >> 1) << 4);
    const int brow = lane & 7;
    const uint32_t bselB = (uint32_t)(((lane >> 3) & 1) * 16);

    // ---- stage 1: signal/gate, 2 taps x K=128 ----
    for (int tap = 0; tap < 2; tap++) {
        const uint32_t bbh = sm_u32(tap ? b1h : b0h);
        const uint32_t bbl = sm_u32(tap ? b1l : b0l);
        for (int kc = 0; kc < 4; kc++) {
            __syncthreads();
            #pragma unroll
            for (int mh = 0; mh < 4; mh++) {
                const uint4* src = (const uint4*)(w1 + (size_t)((tap * 4 + mh) * 4 + kc) * CHUNK);
                uint4* dst = (uint4*)(wsm + mh * CHUNK);
                for (int e2 = t; e2 < 640; e2 += THREADS) dst[e2] = src[e2];
            }
            __syncthreads();
            #pragma unroll
            for (int ks = 0; ks < 2; ks++) {
                uint32_t aoff = (uint32_t)(arow0 * (WPITCH * 2)) + (uint32_t)(ks * 32) + acolB;
                uint32_t aSh[4], aSl[4], aGh[4], aGl[4];
                ldm_x4(aSh, wbase + 0u * 10240u + aoff);
                ldm_x4(aSl, wbase + 1u * 10240u + aoff);
                ldm_x4(aGh, wbase + 2u * 10240u + aoff);
                ldm_x4(aGl, wbase + 3u * 10240u + aoff);
                uint32_t k0B = (uint32_t)((kc * 32 + ks * 16) * 2) + bselB;
                #pragma unroll
                for (int nt = 0; nt < 8; nt++) {
                    uint32_t boff = (uint32_t)((nt * 8 + brow) * (BPITCH * 2)) + k0B;
                    uint32_t bh[2], bl[2];
                    ldm_x2(bh, bbh + boff);
                    ldm_x2(bl, bbl + boff);
                    mma16816(accS[nt], aSh, bh);
                    mma16816(accS[nt], aSh, bl);
                    mma16816(accS[nt], aSl, bh);
                    mma16816(accG[nt], aGh, bh);
                    mma16816(accG[nt], aGh, bl);
                    mma16816(accG[nt], aGl, bh);
                }
            }
        }
    }

    // ---- conditioning + gating: g = signal * sigmoid(gate) ----
    const int ch0 = wid * 16 + gid;
    float gv[8][4];
    {
        float cs0 = csw[ch0], cs1 = csw[ch0 + 8];
        float cg0 = cgw[ch0], cg1 = cgw[ch0 + 8];
        const float* zrow = z + (size_t)b * LEN + l0;
        #pragma unroll
        for (int nt = 0; nt < 8; nt++) {
            int n0 = nt * 8 + tig * 2;
            float z0 = zrow[n0], z1 = zrow[n0 + 1];
            float s0v = accS[nt][0] + cs0 * z0, g0v = accG[nt][0] + cg0 * z0;
            float s1v = accS[nt][1] + cs0 * z1, g1v = accG[nt][1] + cg0 * z1;
            float s2v = accS[nt][2] + cs1 * z0, g2v = accG[nt][2] + cg1 * z0;
            float s3v = accS[nt][3] + cs1 * z1, g3v = accG[nt][3] + cg1 * z1;
            gv[nt][0] = s0v / (1.f + __expf(-g0v));
            gv[nt][1] = s1v / (1.f + __expf(-g1v));
            gv[nt][2] = s2v / (1.f + __expf(-g2v));
            gv[nt][3] = s3v / (1.f + __expf(-g3v));
        }
    }
    __syncthreads();   // all stage-1 reads of b0h/b0l done before overwrite
    #pragma unroll
    for (int nt = 0; nt < 8; nt++) {
        int n0 = nt * 8 + tig * 2;
        #pragma unroll
        for (int j = 0; j < 4; j++) {
            int n  = n0 + (j & 1);
            int ch = ch0 + ((j >> 1) << 3);
            __nv_bfloat16 hi = __float2bfloat16(gv[nt][j]);
            b0h[n * BPITCH + ch] = hi;
            b0l[n * BPITCH + ch] = __float2bfloat16(gv[nt][j] - __bfloat162float(hi));
        }
    }
    #pragma unroll
    for (int i = 0; i < 8; i++)
        #pragma unroll
        for (int j = 0; j < 4; j++) { accS[i][j] = 0.f; accG[i][j] = 0.f; }

    // ---- stage 2: res/skip GEMMs over g (K=128) ----
    {
        const uint32_t bbh = sm_u32(b0h);
        const uint32_t bbl = sm_u32(b0l);
        for (int kc = 0; kc < 4; kc++) {
            __syncthreads();
            #pragma unroll
            for (int mh = 0; mh < 4; mh++) {
                const uint4* src = (const uint4*)(w2 + (size_t)(mh * 4 + kc) * CHUNK);
                uint4* dst = (uint4*)(wsm + mh * CHUNK);
                for (int e2 = t; e2 < 640; e2 += THREADS) dst[e2] = src[e2];
            }
            __syncthreads();
            #pragma unroll
            for (int ks = 0; ks < 2; ks++) {
                uint32_t aoff = (uint32_t)(arow0 * (WPITCH * 2)) + (uint32_t)(ks * 32) + acolB;
                uint32_t aRh[4], aRl[4], aKh[4], aKl[4];
                ldm_x4(aRh, wbase + 0u * 10240u + aoff);
                ldm_x4(aRl, wbase + 1u * 10240u + aoff);
                ldm_x4(aKh, wbase + 2u * 10240u + aoff);
                ldm_x4(aKl, wbase + 3u * 10240u + aoff);
                uint32_t k0B = (uint32_t)((kc * 32 + ks * 16) * 2) + bselB;
                #pragma unroll
                for (int nt = 0; nt < 8; nt++) {
                    uint32_t boff = (uint32_t)((nt * 8 + brow) * (BPITCH * 2)) + k0B;
                    uint32_t bh[2], bl[2];
                    ldm_x2(bh, bbh + boff);
                    ldm_x2(bl, bbl + boff);
                    mma16816(accS[nt], aRh, bh);
                    mma16816(accS[nt], aRh, bl);
                    mma16816(accS[nt], aRl, bh);
                    mma16816(accG[nt], aKh, bh);
                    mma16816(accG[nt], aKh, bl);
                    mma16816(accG[nt], aKl, bh);
                }
            }
        }
    }

    // ---- epilogue: h update + skip accumulation ----
    #pragma unroll
    for (int nt = 0; nt < 8; nt++) {
        int n0 = nt * 8 + tig * 2;
        #pragma unroll
        for (int j = 0; j < 4; j++) {
            int n  = n0 + (j & 1);
            int ch = ch0 + ((j >> 1) << 3);
            size_t idx = (size_t)(b * CH + ch) * LEN + l0 + n;
            float res = accS[nt][j], sk = accG[nt][j];
            float hv = first ? (hin[idx] + res) : (gv[nt][j] + res);
            hout[idx] = hv;
            if (first) skipout[idx] = sk;
            else       skipout[idx] += sk;
        }
    }
}

extern "C" void kernel_launch(void* const* d_in, const int* in_sizes, int n_in,
                              void* d_out, int out_size) {
    (void)in_sizes; (void)n_in; (void)out_size;
    const float* x   = (const float*)d_in[0];
    const float* z   = (const float*)d_in[1];
    const float* w0  = (const float*)d_in[2];
    const float* b0  = (const float*)d_in[3];
    const float* sw  = (const float*)d_in[4];
    const float* gw  = (const float*)d_in[5];
    const float* csw = (const float*)d_in[6];
    const float* cgw = (const float*)d_in[7];
    const float* rw  = (const float*)d_in[8];
    const float* kw  = (const float*)d_in[9];

    float* outH = (float*)d_out;                       // h        (B,C,L)
    float* outS = outH + (size_t)BATCH * CH * LEN;     // cum_skip (B,C,L)

    float *bufA, *bufB;
    cudaGetSymbolAddress((void**)&bufA, g_bufA);
    cudaGetSymbolAddress((void**)&bufB, g_bufB);
    __nv_bfloat16 *w1p, *w2p;
    cudaGetSymbolAddress((void**)&w1p, g_w1);
    cudaGetSymbolAddress((void**)&w2p, g_w2);

    const int SMEM = (4 * 64 * BPITCH + 4 * CHUNK) * 2;   // 110592 bytes
    cudaFuncSetAttribute(layer_mma,
                         cudaFuncAttributeMaxDynamicSharedMemorySize, SMEM);

    prep_w1<<<4096, 256>>>(sw, gw);
    prep_w2<<<2048, 256>>>(rw, kw);
    proj_kernel<<<dim3(LEN / 128, BATCH), THREADS>>>(x, w0, b0, bufA);

    const float* cur = bufA;
    for (int ii = 0; ii < NR; ii++) {
        int d    = 1 << ii;
        int off2 = (ii == 0) ? 2 : d + 1;
        float* nxt = (ii == NR - 1) ? outH : ((cur == bufA) ? bufB : bufA);
        layer_mma<<<dim3(LEN / TL, BATCH), THREADS, SMEM>>>(
            cur, nxt, outS,
            w1p + (size_t)ii * (2 * 2 * 2 * 4 * CHUNK),
            w2p + (size_t)ii * (2 * 2 * 4 * CHUNK),
            csw + ii * CH, cgw + ii * CH,
            z, off2, ii == 0 ? 1 : 0);
        cur = nxt;
    }
}

// round 3
// speedup vs baseline: 3.2539x; 2.3178x over previous
#include <cuda_runtime.h>
#include <cuda_bf16.h>
#include <cstdint>

#define BATCH   32
#define CIN     21
#define CH      128
#define LEN     4096
#define NR      8
#define TL      128
#define THREADS 512
#define BPITCH  136   // bf16 elems per B-tile row ([n][k] layout)
#define WPITCH  40    // bf16 elems per A row ([m][k] chunk, 32 k + pad)
#define CHUNK   5120  // 128*WPITCH elems per matrix chunk

// ---------------- device scratch (no cudaMalloc allowed) ----------------
__device__ float g_bufA[(size_t)BATCH * CH * LEN];
__device__ float g_bufB[(size_t)BATCH * CH * LEN];
// stage1 weights: [layer][tap][kc4][mh4: Sh,Sl,Gh,Gl][m128][WPITCH]
__device__ __nv_bfloat16 g_w1[(size_t)NR * 2 * 4 * 4 * CHUNK];
// stage2 weights: [layer][kc4][mh4: Rh,Rl,Kh,Kl][m128][WPITCH]
__device__ __nv_bfloat16 g_w2[(size_t)NR * 4 * 4 * CHUNK];

// ---------------- helpers ----------------
__device__ __forceinline__ uint32_t sm_u32(const void* p) {
    return (uint32_t)__cvta_generic_to_shared(p);
}
__device__ __forceinline__ void ldm_x4(uint32_t* r, uint32_t addr) {
    asm volatile("ldmatrix.sync.aligned.m8n8.x4.shared.b16 {%0,%1,%2,%3}, [%4];"
                 : "=r"(r[0]), "=r"(r[1]), "=r"(r[2]), "=r"(r[3]) : "r"(addr));
}
__device__ __forceinline__ void ldm_x2(uint32_t* r, uint32_t addr) {
    asm volatile("ldmatrix.sync.aligned.m8n8.x2.shared.b16 {%0,%1}, [%2];"
                 : "=r"(r[0]), "=r"(r[1]) : "r"(addr));
}
__device__ __forceinline__ void mma16816(float* c, const uint32_t* a, const uint32_t* b) {
    asm volatile("mma.sync.aligned.m16n8k16.row.col.f32.bf16.bf16.f32 "
                 "{%0,%1,%2,%3}, {%4,%5,%6,%7}, {%8,%9}, {%0,%1,%2,%3};"
                 : "+f"(c[0]), "+f"(c[1]), "+f"(c[2]), "+f"(c[3])
                 : "r"(a[0]), "r"(a[1]), "r"(a[2]), "r"(a[3]),
                   "r"(b[0]), "r"(b[1]));
}
__device__ __forceinline__ void cpa16(uint32_t saddr, const void* g) {
    asm volatile("cp.async.cg.shared.global [%0], [%1], 16;" :: "r"(saddr), "l"(g));
}
__device__ __forceinline__ void cp_commit() { asm volatile("cp.async.commit_group;"); }
__device__ __forceinline__ void cp_wait0()  { asm volatile("cp.async.wait_group 0;"); }

// copy one 40KB weight round (4 matrices) global -> smem via cp.async
__device__ __forceinline__ void stage_round(const __nv_bfloat16* gsrc,
                                            __nv_bfloat16* sdst, int t) {
    const uint4* g = (const uint4*)gsrc;
    uint32_t s = sm_u32(sdst);
    #pragma unroll
    for (int i = 0; i < 5; i++)
        cpa16(s + (uint32_t)(t + i * THREADS) * 16u, g + t + i * THREADS);
}

// ---------------- weight prep: split fp32 -> bf16 hi/lo, ldmatrix layout ----------------
__global__ void prep_w1(const float* __restrict__ sw, const float* __restrict__ gw) {
    int idx = blockIdx.x * blockDim.x + threadIdx.x;
    if (idx >= NR * 2 * 2 * 4 * 128 * 32) return;
    int kk = idx & 31; int r = idx >> 5;
    int m  = r & 127;  r >>= 7;
    int kc = r & 3;    r >>= 2;
    int mat = r & 1;   r >>= 1;
    int tap = r & 1;   r >>= 1;
    int layer = r;
    int i = kc * 32 + kk;
    const float* src = mat ? gw : sw;
    float v = src[(((size_t)layer * CH + m) * CH + i) * 2 + tap];
    __nv_bfloat16 hi = __float2bfloat16(v);
    __nv_bfloat16 lo = __float2bfloat16(v - __bfloat162float(hi));
    size_t hbase = ((size_t)((((layer * 2 + tap) * 4 + kc) * 4) + mat * 2)) * CHUNK
                 + (size_t)m * WPITCH + kk;
    g_w1[hbase] = hi;
    g_w1[hbase + CHUNK] = lo;
}

__global__ void prep_w2(const float* __restrict__ rw, const float* __restrict__ kw) {
    int idx = blockIdx.x * blockDim.x + threadIdx.x;
    if (idx >= NR * 2 * 4 * 128 * 32) return;
    int kk = idx & 31; int r = idx >> 5;
    int m  = r & 127;  r >>= 7;
    int kc = r & 3;    r >>= 2;
    int mat = r & 1;   r >>= 1;
    int layer = r;
    int i = kc * 32 + kk;
    const float* src = mat ? kw : rw;
    float v = src[((size_t)layer * CH + m) * CH + i];
    __nv_bfloat16 hi = __float2bfloat16(v);
    __nv_bfloat16 lo = __float2bfloat16(v - __bfloat162float(hi));
    size_t hbase = ((size_t)(((layer * 4 + kc) * 4) + mat * 2)) * CHUNK
                 + (size_t)m * WPITCH + kk;
    g_w2[hbase] = hi;
    g_w2[hbase + CHUNK] = lo;
}

// ---------------- initial projection: h0 = w0 @ x + b0 ----------------
__global__ void __launch_bounds__(256) proj_kernel(
    const float* __restrict__ x, const float* __restrict__ w0,
    const float* __restrict__ b0, float* __restrict__ h)
{
    __shared__ float xs[CIN][128];
    __shared__ float ws[CH][CIN];
    __shared__ float bs[CH];

    const int b  = blockIdx.y;
    const int l0 = blockIdx.x * 128;
    const int t  = threadIdx.x;

    for (int e = t; e < CIN * 128; e += 256) {
        int i = e >> 7, l = e & 127;
        xs[i][l] = x[((size_t)b * CIN + i) * LEN + l0 + l];
    }
    for (int e = t; e < CH * CIN; e += 256)
        ws[e / CIN][e % CIN] = w0[e];
    if (t < CH) bs[t] = b0[t];
    __syncthreads();

    const int w = t >> 5, lane = t & 31;
    for (int oo = 0; oo < 16; oo++) {
        int o = w * 16 + oo;
        float a0 = bs[o], a1 = bs[o], a2 = bs[o], a3 = bs[o];
        #pragma unroll
        for (int i = 0; i < CIN; i++) {
            float wv = ws[o][i];
            a0 += wv * xs[i][lane];
            a1 += wv * xs[i][lane + 32];
            a2 += wv * xs[i][lane + 64];
            a3 += wv * xs[i][lane + 96];
        }
        float* dst = h + ((size_t)b * CH + o) * LEN + l0;
        dst[lane] = a0; dst[lane + 32] = a1; dst[lane + 64] = a2; dst[lane + 96] = a3;
    }
}

// ---------------- one WaveNet layer via mma.sync bf16x2, 512 threads ----------------
// taps: tap0 at (l - off2), tap1 at (l - 1)
__global__ void __launch_bounds__(THREADS, 1) layer_mma(
    const float* __restrict__ hin, float* __restrict__ hout,
    float* __restrict__ skipout,
    const __nv_bfloat16* __restrict__ w1, const __nv_bfloat16* __restrict__ w2,
    const float* __restrict__ csw, const float* __restrict__ cgw,
    const float* __restrict__ z, int off2, int first)
{
    extern __shared__ __align__(16) unsigned char smraw[];
    __nv_bfloat16* b0h = (__nv_bfloat16*)smraw;          // [TL][BPITCH]
    __nv_bfloat16* b0l = b0h + TL * BPITCH;
    __nv_bfloat16* b1h = b0l + TL * BPITCH;
    __nv_bfloat16* b1l = b1h + TL * BPITCH;
    __nv_bfloat16* wsm = b1l + TL * BPITCH;              // 2 x [4][128][WPITCH]

    const int t = threadIdx.x, wid = t >> 5, lane = t & 31;
    const int mg = wid & 7, ng = wid >> 3;               // M-group, N-half
    const int gid = lane >> 2, tig = lane & 3;
    const int b = blockIdx.y, l0 = blockIdx.x * TL;

    // prologue: prefetch stage-1 round 0 while loading B windows
    stage_round(w1, wsm, t);
    cp_commit();

    // ---- load both shifted B windows, convert to bf16 hi/lo, [n][k] layout ----
    {
        const int s0 = l0 - off2, s1 = l0 - 1;
        for (int e = t; e < CH * TL; e += THREADS) {
            int ch = e >> 7, p = e & 127;
            const float* row = hin + (size_t)(b * CH + ch) * LEN;
            int q0 = s0 + p, q1 = s1 + p;
            float v0 = (q0 >= 0) ? row[q0] : 0.f;
            float v1 = (q1 >= 0) ? row[q1] : 0.f;
            __nv_bfloat16 h0 = __float2bfloat16(v0);
            b0h[p * BPITCH + ch] = h0;
            b0l[p * BPITCH + ch] = __float2bfloat16(v0 - __bfloat162float(h0));
            __nv_bfloat16 h1 = __float2bfloat16(v1);
            b1h[p * BPITCH + ch] = h1;
            b1l[p * BPITCH + ch] = __float2bfloat16(v1 - __bfloat162float(h1));
        }
    }
    cp_wait0();
    __syncthreads();

    float accS[8][4], accG[8][4];
    #pragma unroll
    for (int i = 0; i < 8; i++)
        #pragma unroll
        for (int j = 0; j < 4; j++) { accS[i][j] = 0.f; accG[i][j] = 0.f; }

    const int sel   = lane >> 3;
    const int arow0 = mg * 16 + ((sel & 1) << 3) + (lane & 7);
    const uint32_t aoffbase = (uint32_t)(arow0 * (WPITCH * 2)) + (uint32_t)((sel >> 1) << 4);
    const int brow = lane & 7;
    const uint32_t bselB = (uint32_t)(((lane >> 3) & 1) * 16);
    const int nbase = ng * 64;

    // ---- stage 1: signal/gate, 8 rounds (tap x kc) ----
    for (int r = 0; r < 8; r++) {
        const int tap = r >> 2, kc = r & 3;
        if (r + 1 < 8) {
            stage_round(w1 + (size_t)(r + 1) * 4 * CHUNK, wsm + ((r + 1) & 1) * 4 * CHUNK, t);
            cp_commit();
        }
        const uint32_t wbase = sm_u32(wsm + (r & 1) * 4 * CHUNK);
        const uint32_t bbh = sm_u32(tap ? b1h : b0h);
        const uint32_t bbl = sm_u32(tap ? b1l : b0l);
        #pragma unroll
        for (int ks = 0; ks < 2; ks++) {
            uint32_t aoff = aoffbase + (uint32_t)(ks * 32);
            uint32_t aSh[4], aSl[4], aGh[4], aGl[4];
            ldm_x4(aSh, wbase + 0u * 10240u + aoff);
            ldm_x4(aSl, wbase + 1u * 10240u + aoff);
            ldm_x4(aGh, wbase + 2u * 10240u + aoff);
            ldm_x4(aGl, wbase + 3u * 10240u + aoff);
            uint32_t k0B = (uint32_t)((kc * 32 + ks * 16) * 2) + bselB;
            #pragma unroll
            for (int nt = 0; nt < 8; nt++) {
                uint32_t boff = (uint32_t)((nbase + nt * 8 + brow) * (BPITCH * 2)) + k0B;
                uint32_t bh[2], bl[2];
                ldm_x2(bh, bbh + boff);
                ldm_x2(bl, bbl + boff);
                mma16816(accS[nt], aSh, bh);
                mma16816(accS[nt], aSh, bl);
                mma16816(accS[nt], aSl, bh);
                mma16816(accG[nt], aGh, bh);
                mma16816(accG[nt], aGh, bl);
                mma16816(accG[nt], aGl, bh);
            }
        }
        cp_wait0();
        __syncthreads();
    }

    // prefetch stage-2 round 0 (into buf 0; last read of buf 0 was round 6)
    stage_round(w2, wsm, t);
    cp_commit();

    // ---- conditioning + gating: g = signal * sigmoid(gate) -> smem hi/lo ----
    const int ch0 = mg * 16 + gid;
    {
        float cs0 = csw[ch0], cs1 = csw[ch0 + 8];
        float cg0 = cgw[ch0], cg1 = cgw[ch0 + 8];
        const float* zrow = z + (size_t)b * LEN + l0 + nbase;
        float gv[8][4];
        #pragma unroll
        for (int nt = 0; nt < 8; nt++) {
            int n0 = nt * 8 + tig * 2;
            float z0 = zrow[n0], z1 = zrow[n0 + 1];
            float s0v = accS[nt][0] + cs0 * z0, g0v = accG[nt][0] + cg0 * z0;
            float s1v = accS[nt][1] + cs0 * z1, g1v = accG[nt][1] + cg0 * z1;
            float s2v = accS[nt][2] + cs1 * z0, g2v = accG[nt][2] + cg1 * z0;
            float s3v = accS[nt][3] + cs1 * z1, g3v = accG[nt][3] + cg1 * z1;
            gv[nt][0] = s0v / (1.f + __expf(-g0v));
            gv[nt][1] = s1v / (1.f + __expf(-g1v));
            gv[nt][2] = s2v / (1.f + __expf(-g2v));
            gv[nt][3] = s3v / (1.f + __expf(-g3v));
        }
        __syncthreads();   // all stage-1 reads of b0h/b0l done before overwrite
        #pragma unroll
        for (int nt = 0; nt < 8; nt++) {
            int n0 = nbase + nt * 8 + tig * 2;
            #pragma unroll
            for (int j = 0; j < 4; j++) {
                int n  = n0 + (j & 1);
                int ch = ch0 + ((j >> 1) << 3);
                __nv_bfloat16 hi = __float2bfloat16(gv[nt][j]);
                b0h[n * BPITCH + ch] = hi;
                b0l[n * BPITCH + ch] = __float2bfloat16(gv[nt][j] - __bfloat162float(hi));
            }
        }
    }
    #pragma unroll
    for (int i = 0; i < 8; i++)
        #pragma unroll
        for (int j = 0; j < 4; j++) { accS[i][j] = 0.f; accG[i][j] = 0.f; }
    cp_wait0();
    __syncthreads();

    // ---- stage 2: res/skip GEMMs over g (K=128), 4 rounds ----
    {
        const uint32_t bbh = sm_u32(b0h);
        const uint32_t bbl = sm_u32(b0l);
        for (int r = 0; r < 4; r++) {
            const int kc = r;
            if (r + 1 < 4) {
                stage_round(w2 + (size_t)(r + 1) * 4 * CHUNK, wsm + ((r + 1) & 1) * 4 * CHUNK, t);
                cp_commit();
            }
            const uint32_t wbase = sm_u32(wsm + (r & 1) * 4 * CHUNK);
            #pragma unroll
            for (int ks = 0; ks < 2; ks++) {
                uint32_t aoff = aoffbase + (uint32_t)(ks * 32);
                uint32_t aRh[4], aRl[4], aKh[4], aKl[4];
                ldm_x4(aRh, wbase + 0u * 10240u + aoff);
                ldm_x4(aRl, wbase + 1u * 10240u + aoff);
                ldm_x4(aKh, wbase + 2u * 10240u + aoff);
                ldm_x4(aKl, wbase + 3u * 10240u + aoff);
                uint32_t k0B = (uint32_t)((kc * 32 + ks * 16) * 2) + bselB;
                #pragma unroll
                for (int nt = 0; nt < 8; nt++) {
                    uint32_t boff = (uint32_t)((nbase + nt * 8 + brow) * (BPITCH * 2)) + k0B;
                    uint32_t bh[2], bl[2];
                    ldm_x2(bh, bbh + boff);
                    ldm_x2(bl, bbl + boff);
                    mma16816(accS[nt], aRh, bh);
                    mma16816(accS[nt], aRh, bl);
                    mma16816(accS[nt], aRl, bh);
                    mma16816(accG[nt], aKh, bh);
                    mma16816(accG[nt], aKh, bl);
                    mma16816(accG[nt], aKl, bh);
                }
            }
            cp_wait0();
            __syncthreads();
        }
    }

    // ---- epilogue: h update + skip accumulation ----
    #pragma unroll
    for (int nt = 0; nt < 8; nt++) {
        int n0 = nbase + nt * 8 + tig * 2;
        #pragma unroll
        for (int j = 0; j < 4; j++) {
            int n  = n0 + (j & 1);
            int ch = ch0 + ((j >> 1) << 3);
            size_t idx = (size_t)(b * CH + ch) * LEN + l0 + n;
            float res = accS[nt][j], sk = accG[nt][j];
            float hv;
            if (first) {
                hv = hin[idx] + res;
            } else {
                float g = __bfloat162float(b0h[n * BPITCH + ch]) +
                          __bfloat162float(b0l[n * BPITCH + ch]);
                hv = g + res;
            }
            hout[idx] = hv;
            if (first) skipout[idx] = sk;
            else       skipout[idx] += sk;
        }
    }
}

extern "C" void kernel_launch(void* const* d_in, const int* in_sizes, int n_in,
                              void* d_out, int out_size) {
    (void)in_sizes; (void)n_in; (void)out_size;
    const float* x   = (const float*)d_in[0];
    const float* z   = (const float*)d_in[1];
    const float* w0  = (const float*)d_in[2];
    const float* b0  = (const float*)d_in[3];
    const float* sw  = (const float*)d_in[4];
    const float* gw  = (const float*)d_in[5];
    const float* csw = (const float*)d_in[6];
    const float* cgw = (const float*)d_in[7];
    const float* rw  = (const float*)d_in[8];
    const float* kw  = (const float*)d_in[9];

    float* outH = (float*)d_out;                       // h        (B,C,L)
    float* outS = outH + (size_t)BATCH * CH * LEN;     // cum_skip (B,C,L)

    float *bufA, *bufB;
    cudaGetSymbolAddress((void**)&bufA, g_bufA);
    cudaGetSymbolAddress((void**)&bufB, g_bufB);
    __nv_bfloat16 *w1p, *w2p;
    cudaGetSymbolAddress((void**)&w1p, g_w1);
    cudaGetSymbolAddress((void**)&w2p, g_w2);

    const int SMEM = (4 * TL * BPITCH + 2 * 4 * CHUNK) * 2;   // 221184 bytes
    cudaFuncSetAttribute(layer_mma,
                         cudaFuncAttributeMaxDynamicSharedMemorySize, SMEM);

    prep_w1<<<2048, 256>>>(sw, gw);
    prep_w2<<<1024, 256>>>(rw, kw);
    proj_kernel<<<dim3(LEN / 128, BATCH), 256>>>(x, w0, b0, bufA);

    const float* cur = bufA;
    for (int ii = 0; ii < NR; ii++) {
        int d    = 1 << ii;
        int off2 = (ii == 0) ? 2 : d + 1;
        float* nxt = (ii == NR - 1) ? outH : ((cur == bufA) ? bufB : bufA);
        layer_mma<<<dim3(LEN / TL, BATCH), THREADS, SMEM>>>(
            cur, nxt, outS,
            w1p + (size_t)ii * (2 * 4 * 4 * CHUNK),
            w2p + (size_t)ii * (4 * 4 * CHUNK),
            csw + ii * CH, cgw + ii * CH,
            z, off2, ii == 0 ? 1 : 0);
        cur = nxt;
    }
}

// round 4
// speedup vs baseline: 3.2557x; 1.0005x over previous
#include <cuda_runtime.h>
#include <cuda_bf16.h>
#include <cstdint>

#define BATCH   32
#define CIN     21
#define CH      128
#define LEN     4096
#define NR      8
#define TL      128
#define THREADS 512
#define BPITCH  136   // bf16 elems per B-tile row ([n][k] layout)
#define WPITCH  40    // bf16 elems per A row ([m][k] chunk, 32 k + pad)
#define CHUNK   5120  // 128*WPITCH elems per matrix chunk

// ---------------- device scratch (no cudaMalloc allowed) ----------------
__device__ float g_bufA[(size_t)BATCH * CH * LEN];
__device__ float g_bufB[(size_t)BATCH * CH * LEN];
// stage1 weights: [layer][tap][kc4][mh4: Sh,Sl,Gh,Gl][m128][WPITCH]
__device__ __nv_bfloat16 g_w1[(size_t)NR * 2 * 4 * 4 * CHUNK];
// stage2 weights: [layer][kc4][mh4: Rh,Rl,Kh,Kl][m128][WPITCH]
__device__ __nv_bfloat16 g_w2[(size_t)NR * 4 * 4 * CHUNK];

// ---------------- helpers ----------------
__device__ __forceinline__ uint32_t sm_u32(const void* p) {
    return (uint32_t)__cvta_generic_to_shared(p);
}
__device__ __forceinline__ void ldm_x4(uint32_t* r, uint32_t addr) {
    asm volatile("ldmatrix.sync.aligned.m8n8.x4.shared.b16 {%0,%1,%2,%3}, [%4];"
                 : "=r"(r[0]), "=r"(r[1]), "=r"(r[2]), "=r"(r[3]) : "r"(addr));
}
__device__ __forceinline__ void ldm_x2(uint32_t* r, uint32_t addr) {
    asm volatile("ldmatrix.sync.aligned.m8n8.x2.shared.b16 {%0,%1}, [%2];"
                 : "=r"(r[0]), "=r"(r[1]) : "r"(addr));
}
__device__ __forceinline__ void mma16816(float* c, const uint32_t* a, const uint32_t* b) {
    asm volatile("mma.sync.aligned.m16n8k16.row.col.f32.bf16.bf16.f32 "
                 "{%0,%1,%2,%3}, {%4,%5,%6,%7}, {%8,%9}, {%0,%1,%2,%3};"
                 : "+f"(c[0]), "+f"(c[1]), "+f"(c[2]), "+f"(c[3])
                 : "r"(a[0]), "r"(a[1]), "r"(a[2]), "r"(a[3]),
                   "r"(b[0]), "r"(b[1]));
}
__device__ __forceinline__ void cpa16(uint32_t saddr, const void* g) {
    asm volatile("cp.async.cg.shared.global [%0], [%1], 16;" :: "r"(saddr), "l"(g));
}
__device__ __forceinline__ void cp_commit() { asm volatile("cp.async.commit_group;"); }
__device__ __forceinline__ void cp_wait0()  { asm volatile("cp.async.wait_group 0;"); }

// copy one 40KB weight round (4 matrices) global -> smem via cp.async
__device__ __forceinline__ void stage_round(const __nv_bfloat16* gsrc,
                                            __nv_bfloat16* sdst, int t) {
    const uint4* g = (const uint4*)gsrc;
    uint32_t s = sm_u32(sdst);
    #pragma unroll
    for (int i = 0; i < 5; i++)
        cpa16(s + (uint32_t)(t + i * THREADS) * 16u, g + t + i * THREADS);
}

// ---------------- weight prep: split fp32 -> bf16 hi/lo, ldmatrix layout ----------------
__global__ void prep_w1(const float* __restrict__ sw, const float* __restrict__ gw) {
    int idx = blockIdx.x * blockDim.x + threadIdx.x;
    if (idx >= NR * 2 * 2 * 4 * 128 * 32) return;
    int kk = idx & 31; int r = idx >> 5;
    int m  = r & 127;  r >>= 7;
    int kc = r & 3;    r >>= 2;
    int mat = r & 1;   r >>= 1;
    int tap = r & 1;   r >>= 1;
    int layer = r;
    int i = kc * 32 + kk;
    const float* src = mat ? gw : sw;
    float v = src[(((size_t)layer * CH + m) * CH + i) * 2 + tap];
    __nv_bfloat16 hi = __float2bfloat16(v);
    __nv_bfloat16 lo = __float2bfloat16(v - __bfloat162float(hi));
    size_t hbase = ((size_t)((((layer * 2 + tap) * 4 + kc) * 4) + mat * 2)) * CHUNK
                 + (size_t)m * WPITCH + kk;
    g_w1[hbase] = hi;
    g_w1[hbase + CHUNK] = lo;
}

__global__ void prep_w2(const float* __restrict__ rw, const float* __restrict__ kw) {
    int idx = blockIdx.x * blockDim.x + threadIdx.x;
    if (idx >= NR * 2 * 4 * 128 * 32) return;
    int kk = idx & 31; int r = idx >> 5;
    int m  = r & 127;  r >>= 7;
    int kc = r & 3;    r >>= 2;
    int mat = r & 1;   r >>= 1;
    int layer = r;
    int i = kc * 32 + kk;
    const float* src = mat ? kw : rw;
    float v = src[((size_t)layer * CH + m) * CH + i];
    __nv_bfloat16 hi = __float2bfloat16(v);
    __nv_bfloat16 lo = __float2bfloat16(v - __bfloat162float(hi));
    size_t hbase = ((size_t)(((layer * 4 + kc) * 4) + mat * 2)) * CHUNK
                 + (size_t)m * WPITCH + kk;
    g_w2[hbase] = hi;
    g_w2[hbase + CHUNK] = lo;
}

// ---------------- initial projection: h0 = w0 @ x + b0 ----------------
__global__ void __launch_bounds__(256) proj_kernel(
    const float* __restrict__ x, const float* __restrict__ w0,
    const float* __restrict__ b0, float* __restrict__ h)
{
    __shared__ float xs[CIN][128];
    __shared__ float ws[CH][CIN];
    __shared__ float bs[CH];

    const int b  = blockIdx.y;
    const int l0 = blockIdx.x * 128;
    const int t  = threadIdx.x;

    for (int e = t; e < CIN * 128; e += 256) {
        int i = e >> 7, l = e & 127;
        xs[i][l] = x[((size_t)b * CIN + i) * LEN + l0 + l];
    }
    for (int e = t; e < CH * CIN; e += 256)
        ws[e / CIN][e % CIN] = w0[e];
    if (t < CH) bs[t] = b0[t];
    __syncthreads();

    const int w = t >> 5, lane = t & 31;
    for (int oo = 0; oo < 16; oo++) {
        int o = w * 16 + oo;
        float a0 = bs[o], a1 = bs[o], a2 = bs[o], a3 = bs[o];
        #pragma unroll
        for (int i = 0; i < CIN; i++) {
            float wv = ws[o][i];
            a0 += wv * xs[i][lane];
            a1 += wv * xs[i][lane + 32];
            a2 += wv * xs[i][lane + 64];
            a3 += wv * xs[i][lane + 96];
        }
        float* dst = h + ((size_t)b * CH + o) * LEN + l0;
        dst[lane] = a0; dst[lane + 32] = a1; dst[lane + 64] = a2; dst[lane + 96] = a3;
    }
}

// ---------------- one WaveNet layer via mma.sync bf16x2, 512 threads ----------------
// taps: tap0 at (l - off2), tap1 at (l - 1)
__global__ void __launch_bounds__(THREADS, 1) layer_mma(
    const float* __restrict__ hin, float* __restrict__ hout,
    float* __restrict__ skipout,
    const __nv_bfloat16* __restrict__ w1, const __nv_bfloat16* __restrict__ w2,
    const float* __restrict__ csw, const float* __restrict__ cgw,
    const float* __restrict__ z, int off2, int first)
{
    extern __shared__ __align__(16) unsigned char smraw[];
    __nv_bfloat16* b0h = (__nv_bfloat16*)smraw;          // [TL][BPITCH]
    __nv_bfloat16* b0l = b0h + TL * BPITCH;
    __nv_bfloat16* b1h = b0l + TL * BPITCH;
    __nv_bfloat16* b1l = b1h + TL * BPITCH;
    __nv_bfloat16* wsm = b1l + TL * BPITCH;              // 2 x [4][128][WPITCH]

    const int t = threadIdx.x, wid = t >> 5, lane = t & 31;
    const int mg = wid & 7, ng = wid >> 3;               // M-group, N-half
    const int gid = lane >> 2, tig = lane & 3;
    const int b = blockIdx.y, l0 = blockIdx.x * TL;

    // prologue: prefetch stage-1 round 0 while loading B windows
    stage_round(w1, wsm, t);
    cp_commit();

    // ---- load both shifted B windows, convert to bf16 hi/lo, [n][k] layout ----
    {
        const int s0 = l0 - off2, s1 = l0 - 1;
        for (int e = t; e < CH * TL; e += THREADS) {
            int ch = e >> 7, p = e & 127;
            const float* row = hin + (size_t)(b * CH + ch) * LEN;
            int q0 = s0 + p, q1 = s1 + p;
            float v0 = (q0 >= 0) ? row[q0] : 0.f;
            float v1 = (q1 >= 0) ? row[q1] : 0.f;
            __nv_bfloat16 h0 = __float2bfloat16(v0);
            b0h[p * BPITCH + ch] = h0;
            b0l[p * BPITCH + ch] = __float2bfloat16(v0 - __bfloat162float(h0));
            __nv_bfloat16 h1 = __float2bfloat16(v1);
            b1h[p * BPITCH + ch] = h1;
            b1l[p * BPITCH + ch] = __float2bfloat16(v1 - __bfloat162float(h1));
        }
    }
    cp_wait0();
    __syncthreads();

    float accS[8][4], accG[8][4];
    #pragma unroll
    for (int i = 0; i < 8; i++)
        #pragma unroll
        for (int j = 0; j < 4; j++) { accS[i][j] = 0.f; accG[i][j] = 0.f; }

    const int sel   = lane >> 3;
    const int arow0 = mg * 16 + ((sel & 1) << 3) + (lane & 7);
    const uint32_t aoffbase = (uint32_t)(arow0 * (WPITCH * 2)) + (uint32_t)((sel >> 1) << 4);
    const int brow = lane & 7;
    const uint32_t bselB = (uint32_t)(((lane >> 3) & 1) * 16);
    const int nbase = ng * 64;

    // ---- stage 1: signal/gate, 8 rounds (tap x kc) ----
    for (int r = 0; r < 8; r++) {
        const int tap = r >> 2, kc = r & 3;
        if (r + 1 < 8) {
            stage_round(w1 + (size_t)(r + 1) * 4 * CHUNK, wsm + ((r + 1) & 1) * 4 * CHUNK, t);
            cp_commit();
        }
        const uint32_t wbase = sm_u32(wsm + (r & 1) * 4 * CHUNK);
        const uint32_t bbh = sm_u32(tap ? b1h : b0h);
        const uint32_t bbl = sm_u32(tap ? b1l : b0l);
        #pragma unroll
        for (int ks = 0; ks < 2; ks++) {
            uint32_t aoff = aoffbase + (uint32_t)(ks * 32);
            uint32_t aSh[4], aSl[4], aGh[4], aGl[4];
            ldm_x4(aSh, wbase + 0u * 10240u + aoff);
            ldm_x4(aSl, wbase + 1u * 10240u + aoff);
            ldm_x4(aGh, wbase + 2u * 10240u + aoff);
            ldm_x4(aGl, wbase + 3u * 10240u + aoff);
            uint32_t k0B = (uint32_t)((kc * 32 + ks * 16) * 2) + bselB;
            #pragma unroll
            for (int nt = 0; nt < 8; nt++) {
                uint32_t boff = (uint32_t)((nbase + nt * 8 + brow) * (BPITCH * 2)) + k0B;
                uint32_t bh[2], bl[2];
                ldm_x2(bh, bbh + boff);
                ldm_x2(bl, bbl + boff);
                mma16816(accS[nt], aSh, bh);
                mma16816(accS[nt], aSh, bl);
                mma16816(accS[nt], aSl, bh);
                mma16816(accG[nt], aGh, bh);
                mma16816(accG[nt], aGh, bl);
                mma16816(accG[nt], aGl, bh);
            }
        }
        cp_wait0();
        __syncthreads();
    }

    // prefetch stage-2 round 0 (into buf 0; last read of buf 0 was round 6)
    stage_round(w2, wsm, t);
    cp_commit();

    // ---- conditioning + gating: g = signal * sigmoid(gate) -> smem hi/lo ----
    const int ch0 = mg * 16 + gid;
    {
        float cs0 = csw[ch0], cs1 = csw[ch0 + 8];
        float cg0 = cgw[ch0], cg1 = cgw[ch0 + 8];
        const float* zrow = z + (size_t)b * LEN + l0 + nbase;
        float gv[8][4];
        #pragma unroll
        for (int nt = 0; nt < 8; nt++) {
            int n0 = nt * 8 + tig * 2;
            float z0 = zrow[n0], z1 = zrow[n0 + 1];
            float s0v = accS[nt][0] + cs0 * z0, g0v = accG[nt][0] + cg0 * z0;
            float s1v = accS[nt][1] + cs0 * z1, g1v = accG[nt][1] + cg0 * z1;
            float s2v = accS[nt][2] + cs1 * z0, g2v = accG[nt][2] + cg1 * z0;
            float s3v = accS[nt][3] + cs1 * z1, g3v = accG[nt][3] + cg1 * z1;
            gv[nt][0] = s0v / (1.f + __expf(-g0v));
            gv[nt][1] = s1v / (1.f + __expf(-g1v));
            gv[nt][2] = s2v / (1.f + __expf(-g2v));
            gv[nt][3] = s3v / (1.f + __expf(-g3v));
        }
        __syncthreads();   // all stage-1 reads of b0h/b0l done before overwrite
        #pragma unroll
        for (int nt = 0; nt < 8; nt++) {
            int n0 = nbase + nt * 8 + tig * 2;
            #pragma unroll
            for (int j = 0; j < 4; j++) {
                int n  = n0 + (j & 1);
                int ch = ch0 + ((j >> 1) << 3);
                __nv_bfloat16 hi = __float2bfloat16(gv[nt][j]);
                b0h[n * BPITCH + ch] = hi;
                b0l[n * BPITCH + ch] = __float2bfloat16(gv[nt][j] - __bfloat162float(hi));
            }
        }
    }
    #pragma unroll
    for (int i = 0; i < 8; i++)
        #pragma unroll
        for (int j = 0; j < 4; j++) { accS[i][j] = 0.f; accG[i][j] = 0.f; }
    cp_wait0();
    __syncthreads();

    // ---- stage 2: res/skip GEMMs over g (K=128), 4 rounds ----
    {
        const uint32_t bbh = sm_u32(b0h);
        const uint32_t bbl = sm_u32(b0l);
        for (int r = 0; r < 4; r++) {
            const int kc = r;
            if (r + 1 < 4) {
                stage_round(w2 + (size_t)(r + 1) * 4 * CHUNK, wsm + ((r + 1) & 1) * 4 * CHUNK, t);
                cp_commit();
            }
            const uint32_t wbase = sm_u32(wsm + (r & 1) * 4 * CHUNK);
            #pragma unroll
            for (int ks = 0; ks < 2; ks++) {
                uint32_t aoff = aoffbase + (uint32_t)(ks * 32);
                uint32_t aRh[4], aRl[4], aKh[4], aKl[4];
                ldm_x4(aRh, wbase + 0u * 10240u + aoff);
                ldm_x4(aRl, wbase + 1u * 10240u + aoff);
                ldm_x4(aKh, wbase + 2u * 10240u + aoff);
                ldm_x4(aKl, wbase + 3u * 10240u + aoff);
                uint32_t k0B = (uint32_t)((kc * 32 + ks * 16) * 2) + bselB;
                #pragma unroll
                for (int nt = 0; nt < 8; nt++) {
                    uint32_t boff = (uint32_t)((nbase + nt * 8 + brow) * (BPITCH * 2)) + k0B;
                    uint32_t bh[2], bl[2];
                    ldm_x2(bh, bbh + boff);
                    ldm_x2(bl, bbl + boff);
                    mma16816(accS[nt], aRh, bh);
                    mma16816(accS[nt], aRh, bl);
                    mma16816(accS[nt], aRl, bh);
                    mma16816(accG[nt], aKh, bh);
                    mma16816(accG[nt], aKh, bl);
                    mma16816(accG[nt], aKl, bh);
                }
            }
            cp_wait0();
            __syncthreads();
        }
    }

    // ---- epilogue: h update + skip accumulation ----
    #pragma unroll
    for (int nt = 0; nt < 8; nt++) {
        int n0 = nbase + nt * 8 + tig * 2;
        #pragma unroll
        for (int j = 0; j < 4; j++) {
            int n  = n0 + (j & 1);
            int ch = ch0 + ((j >> 1) << 3);
            size_t idx = (size_t)(b * CH + ch) * LEN + l0 + n;
            float res = accS[nt][j], sk = accG[nt][j];
            float hv;
            if (first) {
                hv = hin[idx] + res;
            } else {
                float g = __bfloat162float(b0h[n * BPITCH + ch]) +
                          __bfloat162float(b0l[n * BPITCH + ch]);
                hv = g + res;
            }
            hout[idx] = hv;
            if (first) skipout[idx] = sk;
            else       skipout[idx] += sk;
        }
    }
}

extern "C" void kernel_launch(void* const* d_in, const int* in_sizes, int n_in,
                              void* d_out, int out_size) {
    (void)in_sizes; (void)n_in; (void)out_size;
    const float* x   = (const float*)d_in[0];
    const float* z   = (const float*)d_in[1];
    const float* w0  = (const float*)d_in[2];
    const float* b0  = (const float*)d_in[3];
    const float* sw  = (const float*)d_in[4];
    const float* gw  = (const float*)d_in[5];
    const float* csw = (const float*)d_in[6];
    const float* cgw = (const float*)d_in[7];
    const float* rw  = (const float*)d_in[8];
    const float* kw  = (const float*)d_in[9];

    float* outH = (float*)d_out;                       // h        (B,C,L)
    float* outS = outH + (size_t)BATCH * CH * LEN;     // cum_skip (B,C,L)

    float *bufA, *bufB;
    cudaGetSymbolAddress((void**)&bufA, g_bufA);
    cudaGetSymbolAddress((void**)&bufB, g_bufB);
    __nv_bfloat16 *w1p, *w2p;
    cudaGetSymbolAddress((void**)&w1p, g_w1);
    cudaGetSymbolAddress((void**)&w2p, g_w2);

    const int SMEM = (4 * TL * BPITCH + 2 * 4 * CHUNK) * 2;   // 221184 bytes
    cudaFuncSetAttribute(layer_mma,
                         cudaFuncAttributeMaxDynamicSharedMemorySize, SMEM);

    prep_w1<<<2048, 256>>>(sw, gw);
    prep_w2<<<1024, 256>>>(rw, kw);
    proj_kernel<<<dim3(LEN / 128, BATCH), 256>>>(x, w0, b0, bufA);

    const float* cur = bufA;
    for (int ii = 0; ii < NR; ii++) {
        int d    = 1 << ii;
        int off2 = (ii == 0) ? 2 : d + 1;
        float* nxt = (ii == NR - 1) ? outH : ((cur == bufA) ? bufB : bufA);
        layer_mma<<<dim3(LEN / TL, BATCH), THREADS, SMEM>>>(
            cur, nxt, outS,
            w1p + (size_t)ii * (2 * 4 * 4 * CHUNK),
            w2p + (size_t)ii * (4 * 4 * CHUNK),
            csw + ii * CH, cgw + ii * CH,
            z, off2, ii == 0 ? 1 : 0);
        cur = nxt;
    }
}

// round 6
// speedup vs baseline: 3.5514x; 1.0908x over previous
#include <cuda_runtime.h>
#include <cuda_bf16.h>
#include <cstdint>

#define BATCH   32
#define CIN     21
#define CH      128
#define LEN     4096
#define NR      8
#define TL      128
#define THREADS 512
#define BPITCH  136      // bf16 per B row; row stride 272B (conflict-free, proven R3)

// ---------------- device scratch ----------------
__device__ float g_bufA[(size_t)BATCH * CH * LEN];
__device__ float g_bufB[(size_t)BATCH * CH * LEN];
// fragment-major stage1 weights: [layer][slice16: tap,kc,ks][mat4: Sh,Sl,Gh,Gl][mg8][lane32] x uint4
__device__ uint32_t g_w1f[(size_t)NR * 16 * 4 * 8 * 32 * 4];
// stage2: [layer][slice8: kc,ks][mat4: Rh,Rl,Kh,Kl][mg8][lane32] x uint4
__device__ uint32_t g_w2f[(size_t)NR * 8 * 4 * 8 * 32 * 4];

__device__ __forceinline__ uint32_t sm_u32(const void* p) {
    return (uint32_t)__cvta_generic_to_shared(p);
}
__device__ __forceinline__ void ldm_x4(uint32_t* r, uint32_t addr) {
    asm volatile("ldmatrix.sync.aligned.m8n8.x4.shared.b16 {%0,%1,%2,%3}, [%4];"
                 : "=r"(r[0]), "=r"(r[1]), "=r"(r[2]), "=r"(r[3]) : "r"(addr));
}
__device__ __forceinline__ void mma16816(float* c, const uint32_t* a, const uint32_t* b) {
    asm volatile("mma.sync.aligned.m16n8k16.row.col.f32.bf16.bf16.f32 "
                 "{%0,%1,%2,%3}, {%4,%5,%6,%7}, {%8,%9}, {%0,%1,%2,%3};"
                 : "+f"(c[0]), "+f"(c[1]), "+f"(c[2]), "+f"(c[3])
                 : "r"(a[0]), "r"(a[1]), "r"(a[2]), "r"(a[3]),
                   "r"(b[0]), "r"(b[1]));
}

// ---------------- weight prep: fragment-major, bf16 hi/lo split ----------------
__global__ void prep_w1f(const float* __restrict__ sw, const float* __restrict__ gw) {
    int idx = blockIdx.x * blockDim.x + threadIdx.x;
    if (idx >= NR * 16 * 4 * 8 * 32 * 4) return;
    int i    = idx & 3;
    int lane = (idx >> 2) & 31;
    int mgi  = (idx >> 7) & 7;
    int mat  = (idx >> 10) & 3;
    int sl   = (idx >> 12) & 15;
    int layer = idx >> 16;
    int tap = sl >> 3, kc = (sl >> 1) & 3, ks = sl & 1;
    int row  = mgi * 16 + (lane >> 2) + (i & 1) * 8;
    int kcol = kc * 32 + ks * 16 + (lane & 3) * 2 + ((i >> 1) & 1) * 8;
    const float* src = (mat >> 1) ? gw : sw;
    int half = mat & 1;
    float v0 = src[(((size_t)layer * CH + row) * CH + kcol) * 2 + tap];
    float v1 = src[(((size_t)layer * CH + row) * CH + kcol + 1) * 2 + tap];
    __nv_bfloat16 b0, b1;
    if (half) {
        b0 = __float2bfloat16(v0 - __bfloat162float(__float2bfloat16(v0)));
        b1 = __float2bfloat16(v1 - __bfloat162float(__float2bfloat16(v1)));
    } else {
        b0 = __float2bfloat16(v0);
        b1 = __float2bfloat16(v1);
    }
    uint32_t pk = ((uint32_t)__bfloat16_as_ushort(b1) << 16) | __bfloat16_as_ushort(b0);
    size_t o = ((((size_t)layer * 16 + sl) * 4 + mat) * 8 + mgi) * 32 + lane;
    g_w1f[o * 4 + i] = pk;
}

__global__ void prep_w2f(const float* __restrict__ rw, const float* __restrict__ kw) {
    int idx = blockIdx.x * blockDim.x + threadIdx.x;
    if (idx >= NR * 8 * 4 * 8 * 32 * 4) return;
    int i    = idx & 3;
    int lane = (idx >> 2) & 31;
    int mgi  = (idx >> 7) & 7;
    int mat  = (idx >> 10) & 3;
    int sl   = (idx >> 12) & 7;
    int layer = idx >> 15;
    int kc = sl >> 1, ks = sl & 1;
    int row  = mgi * 16 + (lane >> 2) + (i & 1) * 8;
    int kcol = kc * 32 + ks * 16 + (lane & 3) * 2 + ((i >> 1) & 1) * 8;
    const float* src = (mat >> 1) ? kw : rw;
    int half = mat & 1;
    float v0 = src[((size_t)layer * CH + row) * CH + kcol];
    float v1 = src[((size_t)layer * CH + row) * CH + kcol + 1];
    __nv_bfloat16 b0, b1;
    if (half) {
        b0 = __float2bfloat16(v0 - __bfloat162float(__float2bfloat16(v0)));
        b1 = __float2bfloat16(v1 - __bfloat162float(__float2bfloat16(v1)));
    } else {
        b0 = __float2bfloat16(v0);
        b1 = __float2bfloat16(v1);
    }
    uint32_t pk = ((uint32_t)__bfloat16_as_ushort(b1) << 16) | __bfloat16_as_ushort(b0);
    size_t o = ((((size_t)layer * 8 + sl) * 4 + mat) * 8 + mgi) * 32 + lane;
    g_w2f[o * 4 + i] = pk;
}

// ---------------- initial projection ----------------
__global__ void __launch_bounds__(256) proj_kernel(
    const float* __restrict__ x, const float* __restrict__ w0,
    const float* __restrict__ b0, float* __restrict__ h)
{
    __shared__ float xs[CIN][128];
    __shared__ float ws[CH][CIN];
    __shared__ float bs[CH];
    const int b = blockIdx.y, l0 = blockIdx.x * 128, t = threadIdx.x;
    for (int e = t; e < CIN * 128; e += 256) {
        int i = e >> 7, l = e & 127;
        xs[i][l] = x[((size_t)b * CIN + i) * LEN + l0 + l];
    }
    for (int e = t; e < CH * CIN; e += 256) ws[e / CIN][e % CIN] = w0[e];
    if (t < CH) bs[t] = b0[t];
    __syncthreads();
    const int w = t >> 5, lane = t & 31;
    for (int oo = 0; oo < 16; oo++) {
        int o = w * 16 + oo;
        float a0 = bs[o], a1 = bs[o], a2 = bs[o], a3 = bs[o];
        #pragma unroll
        for (int i = 0; i < CIN; i++) {
            float wv = ws[o][i];
            a0 += wv * xs[i][lane];       a1 += wv * xs[i][lane + 32];
            a2 += wv * xs[i][lane + 64];  a3 += wv * xs[i][lane + 96];
        }
        float* dst = h + ((size_t)b * CH + o) * LEN + l0;
        dst[lane] = a0; dst[lane + 32] = a1; dst[lane + 64] = a2; dst[lane + 96] = a3;
    }
}

// ---------------- one WaveNet layer: reg MMA, weights direct from L2 ----------------
__global__ void __launch_bounds__(THREADS, 1) layer_reg(
    const float* __restrict__ hin, float* __restrict__ hout,
    float* __restrict__ skipout,
    const uint4* __restrict__ w1f, const uint4* __restrict__ w2f,
    const float* __restrict__ csw, const float* __restrict__ cgw,
    const float* __restrict__ z, int off2, int first)
{
    extern __shared__ __align__(16) unsigned char smraw[];
    const int SPAN = TL + off2;
    __nv_bfloat16* bwh = (__nv_bfloat16*)smraw;            // [SPAN][BPITCH] hi
    __nv_bfloat16* bwl = bwh + SPAN * BPITCH;              // lo

    const int t = threadIdx.x, wid = t >> 5, lane = t & 31;
    const int mg = wid & 7, ng = wid >> 3;
    const int b = blockIdx.y, l0 = blockIdx.x * TL;

    // ---- fill single shared activation window: row p = h[l0 - off2 + p] ----
    {
        for (int c = 0; c < 8; c++) {
            int ch = wid * 8 + c;
            const float* row = hin + (size_t)(b * CH + ch) * LEN + (l0 - off2);
            for (int p = lane; p < SPAN; p += 32) {
                float v = (l0 - off2 + p >= 0) ? row[p] : 0.f;
                __nv_bfloat16 h = __float2bfloat16(v);
                bwh[p * BPITCH + ch] = h;
                bwl[p * BPITCH + ch] = __float2bfloat16(v - __bfloat162float(h));
            }
        }
    }
    __syncthreads();

    float accS[8][4], accG[8][4];
    #pragma unroll
    for (int i = 0; i < 8; i++)
        #pragma unroll
        for (int j = 0; j < 4; j++) { accS[i][j] = 0.f; accG[i][j] = 0.f; }

    const uint32_t bw_h = sm_u32(bwh), bw_l = sm_u32(bwl);
    const int ntx   = (lane >> 4) & 1;              // which nt within the pair
    const int khalf = (lane >> 3) & 1;              // k half (x4 lane-group select)
    const int brow  = lane & 7;
    const uint32_t rowc = (uint32_t)(ng * 64 + ntx * 8 + brow);

    // ---- stage 1: 16 k-slices (tap x kc x ks), A direct from global ----
    const uint4* wf1 = w1f + (size_t)mg * 32 + lane;
    #pragma unroll 4
    for (int s = 0; s < 16; s++) {
        const int tap = s >> 3, kc = (s >> 1) & 3, ks = s & 1;
        uint4 aSh = wf1[(s * 4 + 0) * 256];
        uint4 aSl = wf1[(s * 4 + 1) * 256];
        uint4 aGh = wf1[(s * 4 + 2) * 256];
        uint4 aGl = wf1[(s * 4 + 3) * 256];
        const uint32_t tbase = tap ? (uint32_t)(off2 - 1) : 0u;
        const uint32_t kb = (uint32_t)((kc * 32 + ks * 16) * 2 + khalf * 16);
        #pragma unroll
        for (int p = 0; p < 4; p++) {
            uint32_t addr = (tbase + rowc + (uint32_t)(p * 16)) * (BPITCH * 2) + kb;
            uint32_t bh[4], bl[4];
            ldm_x4(bh, bw_h + addr);
            ldm_x4(bl, bw_l + addr);
            #pragma unroll
            for (int hnt = 0; hnt < 2; hnt++) {
                int nt = p * 2 + hnt;
                mma16816(accS[nt], (const uint32_t*)&aSh, bh + 2 * hnt);
                mma16816(accS[nt], (const uint32_t*)&aSh, bl + 2 * hnt);
                mma16816(accS[nt], (const uint32_t*)&aSl, bh + 2 * hnt);
                mma16816(accG[nt], (const uint32_t*)&aGh, bh + 2 * hnt);
                mma16816(accG[nt], (const uint32_t*)&aGh, bl + 2 * hnt);
                mma16816(accG[nt], (const uint32_t*)&aGl, bh + 2 * hnt);
            }
        }
    }

    // ---- conditioning + gating ----
    const int gid = lane >> 2, tig = lane & 3;
    const int ch0 = mg * 16 + gid;
    const int nbase = ng * 64;
    {
        float cs0 = csw[ch0], cs1 = csw[ch0 + 8];
        float cg0 = cgw[ch0], cg1 = cgw[ch0 + 8];
        const float* zrow = z + (size_t)b * LEN + l0 + nbase;
        float gv[8][4];
        #pragma unroll
        for (int nt = 0; nt < 8; nt++) {
            int n0 = nt * 8 + tig * 2;
            float z0 = zrow[n0], z1 = zrow[n0 + 1];
            float s0v = accS[nt][0] + cs0 * z0, g0v = accG[nt][0] + cg0 * z0;
            float s1v = accS[nt][1] + cs0 * z1, g1v = accG[nt][1] + cg0 * z1;
            float s2v = accS[nt][2] + cs1 * z0, g2v = accG[nt][2] + cg1 * z0;
            float s3v = accS[nt][3] + cs1 * z1, g3v = accG[nt][3] + cg1 * z1;
            gv[nt][0] = s0v / (1.f + __expf(-g0v));
            gv[nt][1] = s1v / (1.f + __expf(-g1v));
            gv[nt][2] = s2v / (1.f + __expf(-g2v));
            gv[nt][3] = s3v / (1.f + __expf(-g3v));
        }
        __syncthreads();   // all stage-1 window reads complete before overwrite
        #pragma unroll
        for (int nt = 0; nt < 8; nt++) {
            int n0 = nbase + nt * 8 + tig * 2;
            #pragma unroll
            for (int j = 0; j < 4; j++) {
                int n  = n0 + (j & 1);
                int ch = ch0 + ((j >> 1) << 3);
                __nv_bfloat16 hi = __float2bfloat16(gv[nt][j]);
                bwh[n * BPITCH + ch] = hi;
                bwl[n * BPITCH + ch] = __float2bfloat16(gv[nt][j] - __bfloat162float(hi));
            }
        }
    }
    #pragma unroll
    for (int i = 0; i < 8; i++)
        #pragma unroll
        for (int j = 0; j < 4; j++) { accS[i][j] = 0.f; accG[i][j] = 0.f; }
    __syncthreads();

    // ---- stage 2: res/skip over g (rows 0..127 of window) ----
    const uint4* wf2 = w2f + (size_t)mg * 32 + lane;
    #pragma unroll 4
    for (int s = 0; s < 8; s++) {
        const int kc = s >> 1, ks = s & 1;
        uint4 aRh = wf2[(s * 4 + 0) * 256];
        uint4 aRl = wf2[(s * 4 + 1) * 256];
        uint4 aKh = wf2[(s * 4 + 2) * 256];
        uint4 aKl = wf2[(s * 4 + 3) * 256];
        const uint32_t kb = (uint32_t)((kc * 32 + ks * 16) * 2 + khalf * 16);
        #pragma unroll
        for (int p = 0; p < 4; p++) {
            uint32_t addr = (rowc + (uint32_t)(p * 16)) * (BPITCH * 2) + kb;
            uint32_t bh[4], bl[4];
            ldm_x4(bh, bw_h + addr);
            ldm_x4(bl, bw_l + addr);
            #pragma unroll
            for (int hnt = 0; hnt < 2; hnt++) {
                int nt = p * 2 + hnt;
                mma16816(accS[nt], (const uint32_t*)&aRh, bh + 2 * hnt);
                mma16816(accS[nt], (const uint32_t*)&aRh, bl + 2 * hnt);
                mma16816(accS[nt], (const uint32_t*)&aRl, bh + 2 * hnt);
                mma16816(accG[nt], (const uint32_t*)&aKh, bh + 2 * hnt);
                mma16816(accG[nt], (const uint32_t*)&aKh, bl + 2 * hnt);
                mma16816(accG[nt], (const uint32_t*)&aKl, bh + 2 * hnt);
            }
        }
    }

    // ---- epilogue ----
    #pragma unroll
    for (int nt = 0; nt < 8; nt++) {
        int n0 = nbase + nt * 8 + tig * 2;
        #pragma unroll
        for (int j = 0; j < 4; j++) {
            int n  = n0 + (j & 1);
            int ch = ch0 + ((j >> 1) << 3);
            size_t idx = (size_t)(b * CH + ch) * LEN + l0 + n;
            float res = accS[nt][j], sk = accG[nt][j];
            float hv;
            if (first) {
                hv = hin[idx] + res;
            } else {
                float g = __bfloat162float(bwh[n * BPITCH + ch]) +
                          __bfloat162float(bwl[n * BPITCH + ch]);
                hv = g + res;
            }
            hout[idx] = hv;
            if (first) skipout[idx] = sk;
            else       skipout[idx] += sk;
        }
    }
}

extern "C" void kernel_launch(void* const* d_in, const int* in_sizes, int n_in,
                              void* d_out, int out_size) {
    (void)in_sizes; (void)n_in; (void)out_size;
    const float* x   = (const float*)d_in[0];
    const float* z   = (const float*)d_in[1];
    const float* w0  = (const float*)d_in[2];
    const float* b0  = (const float*)d_in[3];
    const float* sw  = (const float*)d_in[4];
    const float* gw  = (const float*)d_in[5];
    const float* csw = (const float*)d_in[6];
    const float* cgw = (const float*)d_in[7];
    const float* rw  = (const float*)d_in[8];
    const float* kw  = (const float*)d_in[9];

    float* outH = (float*)d_out;
    float* outS = outH + (size_t)BATCH * CH * LEN;

    float *bufA, *bufB;
    cudaGetSymbolAddress((void**)&bufA, g_bufA);
    cudaGetSymbolAddress((void**)&bufB, g_bufB);
    uint32_t *w1p, *w2p;
    cudaGetSymbolAddress((void**)&w1p, g_w1f);
    cudaGetSymbolAddress((void**)&w2p, g_w2f);

    const int MAXSMEM = (TL + 129) * BPITCH * 2 * 2;   // layer 7: 139,808 B
    cudaFuncSetAttribute(layer_reg,
                         cudaFuncAttributeMaxDynamicSharedMemorySize, MAXSMEM);

    prep_w1f<<<2048, 256>>>(sw, gw);
    prep_w2f<<<1024, 256>>>(rw, kw);
    proj_kernel<<<dim3(LEN / 128, BATCH), 256>>>(x, w0, b0, bufA);

    const float* cur = bufA;
    for (int ii = 0; ii < NR; ii++) {
        int d    = 1 << ii;
        int off2 = (ii == 0) ? 2 : d + 1;
        int smem = (TL + off2) * BPITCH * 2 * 2;
        float* nxt = (ii == NR - 1) ? outH : ((cur == bufA) ? bufB : bufA);
        layer_reg<<<dim3(LEN / TL, BATCH), THREADS, smem>>>(
            cur, nxt, outS,
            (const uint4*)(w1p + (size_t)ii * 16 * 4 * 8 * 32 * 4),
            (const uint4*)(w2p + (size_t)ii * 8 * 4 * 8 * 32 * 4),
            csw + ii * CH, cgw + ii * CH,
            z, off2, ii == 0 ? 1 : 0);
        cur = nxt;
    }
}